// round 2
// baseline (speedup 1.0000x reference)
#include <cuda_runtime.h>
#include <cuda_bf16.h>

#define NSEG 65
#define EPSF 1e-5f

// Scratch: per-batch (B=2), per-label accumulators.
__device__ float        g_inter[2 * NSEG];
__device__ unsigned int g_cnt[2 * NSEG];
__device__ int          g_is64;   // 1 if y/voronoi are int64, 0 if int32

// ---------------------------------------------------------------------------
// init: zero accumulators + sniff index dtype.
// int64 little-endian with values in [0,64] => every odd 32-bit word is 0.
// int32 => odd words are labels (~1/65 chance each of being 0).
// 128 consecutive zero odd-words: P(false int64) = (1/65)^128 ~ 0.
// ---------------------------------------------------------------------------
__global__ void cc_init_kernel(const unsigned int* __restrict__ vor_words) {
    int i = threadIdx.x;
    if (i < 2 * NSEG) {
        g_inter[i] = 0.0f;
        g_cnt[i]   = 0u;
    }
    if (i == 0) {
        int is64 = 1;
        #pragma unroll 1
        for (int k = 0; k < 128; k++) {
            if (vor_words[2 * k + 1] != 0u) { is64 = 0; break; }
        }
        g_is64 = is64;
    }
}

// ---------------------------------------------------------------------------
// per-voxel: p_true = softmax over C=2 at the true channel = sigmoid(x_y - x_other)
// ---------------------------------------------------------------------------
__device__ __forceinline__ void cc_proc(float x0, float x1, int yv, int sv,
                                        float* s_inter, unsigned int* s_cnt) {
    float d = (yv == 0) ? (x0 - x1) : (x1 - x0);
    float p = __fdividef(1.0f, 1.0f + __expf(-d));
    if (sv != 0) {   // label 0 = background, excluded
        atomicAdd(&s_inter[sv], p);
        atomicAdd(&s_cnt[sv], 1u);
    }
}

__global__ __launch_bounds__(256)
void cc_accum_kernel(const float* __restrict__ pred,
                     const void*  __restrict__ y,
                     const void*  __restrict__ vor,
                     int N) {
    __shared__ float        s_inter[NSEG];
    __shared__ unsigned int s_cnt[NSEG];

    const int b = blockIdx.y;
    for (int i = threadIdx.x; i < NSEG; i += blockDim.x) {
        s_inter[i] = 0.0f;
        s_cnt[i]   = 0u;
    }
    __syncthreads();

    const float* p0 = pred + (size_t)b * 2 * N;
    const float* p1 = p0 + N;
    const float4* x0 = (const float4*)p0;
    const float4* x1 = (const float4*)p1;

    const size_t tid    = (size_t)blockIdx.x * blockDim.x + threadIdx.x;
    const size_t stride = (size_t)gridDim.x * blockDim.x;
    const size_t n4     = (size_t)N >> 2;

    if (g_is64) {
        const longlong2* yb = (const longlong2*)((const long long*)y   + (size_t)b * N);
        const longlong2* vb = (const longlong2*)((const long long*)vor + (size_t)b * N);
        for (size_t i = tid; i < n4; i += stride) {
            // front-batch all 6 x 16B loads -> MLP = 6
            float4    a  = __ldg(&x0[i]);
            float4    c  = __ldg(&x1[i]);
            longlong2 ya = __ldg(&yb[2 * i]);
            longlong2 yc = __ldg(&yb[2 * i + 1]);
            longlong2 va = __ldg(&vb[2 * i]);
            longlong2 vc = __ldg(&vb[2 * i + 1]);
            cc_proc(a.x, c.x, (int)ya.x, (int)va.x, s_inter, s_cnt);
            cc_proc(a.y, c.y, (int)ya.y, (int)va.y, s_inter, s_cnt);
            cc_proc(a.z, c.z, (int)yc.x, (int)vc.x, s_inter, s_cnt);
            cc_proc(a.w, c.w, (int)yc.y, (int)vc.y, s_inter, s_cnt);
        }
        // tail (N % 4) — scalar
        const long long* ys = (const long long*)y   + (size_t)b * N;
        const long long* vs = (const long long*)vor + (size_t)b * N;
        for (size_t i = (n4 << 2) + tid; i < (size_t)N; i += stride)
            cc_proc(p0[i], p1[i], (int)ys[i], (int)vs[i], s_inter, s_cnt);
    } else {
        const int4* yb = (const int4*)((const int*)y   + (size_t)b * N);
        const int4* vb = (const int4*)((const int*)vor + (size_t)b * N);
        for (size_t i = tid; i < n4; i += stride) {
            float4 a  = __ldg(&x0[i]);
            float4 c  = __ldg(&x1[i]);
            int4   yv = __ldg(&yb[i]);
            int4   vv = __ldg(&vb[i]);
            cc_proc(a.x, c.x, yv.x, vv.x, s_inter, s_cnt);
            cc_proc(a.y, c.y, yv.y, vv.y, s_inter, s_cnt);
            cc_proc(a.z, c.z, yv.z, vv.z, s_inter, s_cnt);
            cc_proc(a.w, c.w, yv.w, vv.w, s_inter, s_cnt);
        }
        const int* ys = (const int*)y   + (size_t)b * N;
        const int* vs = (const int*)vor + (size_t)b * N;
        for (size_t i = (n4 << 2) + tid; i < (size_t)N; i += stride)
            cc_proc(p0[i], p1[i], ys[i], vs[i], s_inter, s_cnt);
    }

    __syncthreads();
    for (int i = threadIdx.x; i < NSEG; i += blockDim.x) {
        atomicAdd(&g_inter[b * NSEG + i], s_inter[i]);
        atomicAdd(&g_cnt[b * NSEG + i], s_cnt[i]);
    }
}

// ---------------------------------------------------------------------------
// finalize: psum+tsum == 2*cnt exactly (softmax rows sum to 1), so
// dice = (2*inter + eps) / (2*cnt + eps). Mean over present labels, then batch.
// ---------------------------------------------------------------------------
__global__ void cc_finalize_kernel(float* __restrict__ out) {
    __shared__ float sd[2][64];
    __shared__ float sp[2][64];
    int t = threadIdx.x;  // 0..63 -> label t+1
    for (int b = 0; b < 2; b++) {
        unsigned int c  = g_cnt[b * NSEG + 1 + t];
        float        it = g_inter[b * NSEG + 1 + t];
        float dice = (2.0f * it + EPSF) / (2.0f * (float)c + EPSF);
        sd[b][t] = (c > 0u) ? dice : 0.0f;
        sp[b][t] = (c > 0u) ? 1.0f : 0.0f;
    }
    __syncthreads();
    if (t == 0) {
        float total = 0.0f;
        for (int b = 0; b < 2; b++) {
            float sum = 0.0f, np = 0.0f;
            for (int i = 0; i < 64; i++) { sum += sd[b][i]; np += sp[b][i]; }
            if (np < 1.0f) np = 1.0f;
            total += sum / np;
        }
        out[0] = 0.5f * total;
    }
}

// ---------------------------------------------------------------------------
// launch
// ---------------------------------------------------------------------------
extern "C" void kernel_launch(void* const* d_in, const int* in_sizes, int n_in,
                              void* d_out, int out_size) {
    const float* pred = (const float*)d_in[0];  // y_pred [B,2,H,W,D] f32
    const void*  y    = d_in[1];                // y      [B,1,H,W,D] int64/int32
    const void*  vor  = d_in[2];                // voronoi[B,H,W,D]   int64/int32

    const int B = 2;
    const int N = in_sizes[2] / B;              // voxels per sample (H*W*D)

    cc_init_kernel<<<1, 256>>>((const unsigned int*)vor);

    // 592 x 2 = 1184 blocks = exactly 8 CTAs per SM on 148 SMs
    dim3 grid(592, B);
    cc_accum_kernel<<<grid, 256>>>(pred, y, vor, N);

    cc_finalize_kernel<<<1, 64>>>((float*)d_out);
}